// round 7
// baseline (speedup 1.0000x reference)
#include <cuda_runtime.h>
#include <cuda_bf16.h>
#include <math.h>
#include <stdint.h>

#define D_MODEL 1024
#define NHEAD   16
#define HDIM    64
#define SEQ     2048
#define BATCH   2
#define MTOT    (BATCH * SEQ)   // 4096
#define KP      3072            // split-bf16 K' = 3*1024
#define TK      64              // bf16 per K chunk (128 bytes)
#define NC      (KP / TK)       // 48 chunks
#define LOG2E   1.4426950408889634f

// ---------------- scratch (static device globals: allocation-free) ----------
__device__ float g_Q[BATCH * NHEAD * SEQ * HDIM];   // [b,h,s,d] fp32
__device__ float g_K[BATCH * NHEAD * SEQ * HDIM];
__device__ float g_V[BATCH * NHEAD * SEQ * HDIM];
__device__ __nv_bfloat16 g_Ax[MTOT * KP];           // split x    (A-mode)
__device__ __nv_bfloat16 g_Bq[D_MODEL * KP];        // split W    (B-mode)
__device__ __nv_bfloat16 g_Bk[D_MODEL * KP];
__device__ __nv_bfloat16 g_Bv[D_MODEL * KP];
__device__ __nv_bfloat16 g_Bo[D_MODEL * KP];
__device__ __nv_bfloat16 g_Aatt[MTOT * KP];         // split attn out (A-mode)

// ============================ helpers ========================================
__device__ __forceinline__ uint32_t smem_u32(const void* p) {
    uint32_t a;
    asm("{ .reg .u64 t; cvta.to.shared.u64 t, %1; cvt.u32.u64 %0, t; }"
        : "=r"(a) : "l"(p));
    return a;
}
__device__ __forceinline__ void ldsm4(uint32_t* r, uint32_t addr) {
    asm volatile("ldmatrix.sync.aligned.m8n8.x4.shared.b16 {%0,%1,%2,%3}, [%4];"
                 : "=r"(r[0]), "=r"(r[1]), "=r"(r[2]), "=r"(r[3]) : "r"(addr));
}
__device__ __forceinline__ void mma16816(float* d, const uint32_t* a,
                                         const uint32_t* b) {
    asm volatile(
        "mma.sync.aligned.m16n8k16.row.col.f32.bf16.bf16.f32 "
        "{%0,%1,%2,%3}, {%4,%5,%6,%7}, {%8,%9}, {%0,%1,%2,%3};"
        : "+f"(d[0]), "+f"(d[1]), "+f"(d[2]), "+f"(d[3])
        : "r"(a[0]), "r"(a[1]), "r"(a[2]), "r"(a[3]), "r"(b[0]), "r"(b[1]));
}
// 2^y on the FMA pipe; y <= 0 expected, clamped so -huge -> ~1e-38 (≈0)
__device__ __forceinline__ float exp2p(float y) {
    y = fmaxf(y, -126.0f);
    const int   ni = __float2int_rn(y);
    const float f  = y - (float)ni;
    float p = 0.0096181f;
    p = fmaf(p, f, 0.0555041f);
    p = fmaf(p, f, 0.2402265f);
    p = fmaf(p, f, 0.6931472f);
    p = fmaf(p, f, 1.0f);
    return __int_as_float(__float_as_int(p) + (ni << 23));
}
__device__ __forceinline__ uint32_t pack_bf2(float a, float b) {
    return ((uint32_t)__bfloat16_as_ushort(__float2bfloat16(b)) << 16)
         | __bfloat16_as_ushort(__float2bfloat16(a));
}
// byte offset in a 384B-row (192 bf16 col) swizzled tile
__device__ __forceinline__ uint32_t sw384(int row, int col) {
    return (uint32_t)(row * 384 + ((col >> 6) << 7)
                      + ((((col >> 3) & 7) ^ (row & 7)) << 4) + (col & 7) * 2);
}

// ============================ split kernel ===================================
// bmode 0 (A): [hi | hi | lo]     bmode 1 (B): [hi | lo | hi]
__global__ __launch_bounds__(256) void split_kernel(
    const float* __restrict__ src, __nv_bfloat16* __restrict__ dst, int bmode)
{
    const int idx = blockIdx.x * 256 + threadIdx.x;
    const int row = idx >> 8;
    const int c   = (idx & 255) * 4;
    float4 v = *(const float4*)(src + (size_t)row * 1024 + c);

    __nv_bfloat16 h0 = __float2bfloat16(v.x), h1 = __float2bfloat16(v.y);
    __nv_bfloat16 h2 = __float2bfloat16(v.z), h3 = __float2bfloat16(v.w);
    uint2 hu, lu;
    hu.x = ((uint32_t)__bfloat16_as_ushort(h1) << 16) | __bfloat16_as_ushort(h0);
    hu.y = ((uint32_t)__bfloat16_as_ushort(h3) << 16) | __bfloat16_as_ushort(h2);
    lu.x = pack_bf2(v.x - __bfloat162float(h0), v.y - __bfloat162float(h1));
    lu.y = pack_bf2(v.z - __bfloat162float(h2), v.w - __bfloat162float(h3));

    __nv_bfloat16* p = dst + (size_t)row * KP + c;
    if (bmode) {
        *(uint2*)(p) = hu; *(uint2*)(p + 1024) = lu; *(uint2*)(p + 2048) = hu;
    } else {
        *(uint2*)(p) = hu; *(uint2*)(p + 1024) = hu; *(uint2*)(p + 2048) = lu;
    }
}

// ============================ mma.sync GEMM (validated R5) ===================
#define SMEM_BYTES 65536

__device__ __forceinline__ void ldg_tiles(
    const __nv_bfloat16* __restrict__ A, const __nv_bfloat16* __restrict__ B,
    int bm, int bn, int c, int tid, float4* ar, float4* br)
{
#pragma unroll
    for (int j = 0; j < 4; ++j) {
        const int idx = j * 256 + tid, r = idx >> 3, s = idx & 7;
        ar[j] = *(const float4*)(A + (size_t)(bm + r) * KP + c * TK + s * 8);
        br[j] = *(const float4*)(B + (size_t)(bn + r) * KP + c * TK + s * 8);
    }
}
__device__ __forceinline__ void sts_tiles(
    char* smem, uint32_t pa, uint32_t pb, int tid,
    const float4* ar, const float4* br)
{
#pragma unroll
    for (int j = 0; j < 4; ++j) {
        const int idx = j * 256 + tid, r = idx >> 3, s = idx & 7;
        uint32_t off = (uint32_t)(r * 128 + s * 16);
        off ^= (off >> 3) & 0x70;
        *(float4*)(smem + pa + off) = ar[j];
        *(float4*)(smem + pb + off) = br[j];
    }
}

__global__ __launch_bounds__(256) void gemm_mma(
    const __nv_bfloat16* __restrict__ A, const __nv_bfloat16* __restrict__ B,
    float* __restrict__ C, int mode)
{
    extern __shared__ char smem[];
    const uint32_t sbase = smem_u32(smem);
    const int tid  = threadIdx.x;
    const int warp = tid >> 5;
    const int lane = tid & 31;
    const int bm   = blockIdx.y * 128;
    const int bn   = blockIdx.x * 128;
    const int wm   = warp & 1;
    const int wn   = warp >> 1;

    float4 ar[4], br[4];
    ldg_tiles(A, B, bm, bn, 0, tid, ar, br);
    sts_tiles(smem, 0, 32768, tid, ar, br);
    ldg_tiles(A, B, bm, bn, 1, tid, ar, br);
    __syncthreads();

    float acc[4][4][4];
#pragma unroll
    for (int i = 0; i < 4; ++i)
#pragma unroll
        for (int j = 0; j < 4; ++j)
#pragma unroll
            for (int r = 0; r < 4; ++r) acc[i][j][r] = 0.0f;

    const int arow = (lane & 7) | ((lane >> 3) & 1) << 3;
    const int ach  = (lane >> 4) & 1;
    uint32_t aterm[4]; int asw[4];
#pragma unroll
    for (int i = 0; i < 4; ++i) {
        const int row = wm * 64 + i * 16 + arow;
        aterm[i] = (uint32_t)(row * 128);
        asw[i]   = row & 7;
    }
    const int q   = lane >> 3;
    const int bch = q & 1;
    uint32_t bterm[2]; int bsw[2];
#pragma unroll
    for (int jj = 0; jj < 2; ++jj) {
        const int nrow = wn * 32 + jj * 16 + ((q >> 1) << 3) + (lane & 7);
        bterm[jj] = (uint32_t)(nrow * 128);
        bsw[jj]   = nrow & 7;
    }

    for (int c = 0; c < NC; ++c) {
        const int p = c & 1;
        const uint32_t Ab = sbase + (uint32_t)(p * 16384);
        const uint32_t Bb = sbase + 32768u + (uint32_t)(p * 16384);

        if (c + 1 < NC)
            sts_tiles(smem, (uint32_t)((p ^ 1) * 16384),
                      32768u + (uint32_t)((p ^ 1) * 16384), tid, ar, br);

#pragma unroll
        for (int ks = 0; ks < 4; ++ks) {
            const int k2 = ks * 2;
            uint32_t af[4][4], bf[4][2];
#pragma unroll
            for (int i = 0; i < 4; ++i)
                ldsm4(af[i], Ab + aterm[i] + ((uint32_t)((k2 + ach) ^ asw[i]) << 4));
#pragma unroll
            for (int jj = 0; jj < 2; ++jj) {
                uint32_t t[4];
                ldsm4(t, Bb + bterm[jj] + ((uint32_t)((k2 + bch) ^ bsw[jj]) << 4));
                bf[jj * 2 + 0][0] = t[0]; bf[jj * 2 + 0][1] = t[1];
                bf[jj * 2 + 1][0] = t[2]; bf[jj * 2 + 1][1] = t[3];
            }
#pragma unroll
            for (int i = 0; i < 4; ++i)
#pragma unroll
                for (int j = 0; j < 4; ++j)
                    mma16816(acc[i][j], af[i], bf[j]);
        }

        if (c + 2 < NC) ldg_tiles(A, B, bm, bn, c + 2, tid, ar, br);
        __syncthreads();
    }

    const int g   = lane >> 2;
    const int tig = lane & 3;
#pragma unroll
    for (int i = 0; i < 4; ++i) {
#pragma unroll
        for (int j = 0; j < 4; ++j) {
            const int col = bn + wn * 32 + j * 8 + tig * 2;
            const int m0  = bm + wm * 64 + i * 16 + g;
#pragma unroll
            for (int hrow = 0; hrow < 2; ++hrow) {
                const int m = m0 + hrow * 8;
                const float2 v = make_float2(acc[i][j][hrow * 2],
                                             acc[i][j][hrow * 2 + 1]);
                if (mode == 0) {
                    *(float2*)(C + (size_t)m * D_MODEL + col) = v;
                } else {
                    const int b = m >> 11, s2 = m & 2047;
                    const int h = col >> 6, dd = col & 63;
                    *(float2*)(C + ((((size_t)b * NHEAD + h) * SEQ + s2) * HDIM + dd)) = v;
                }
            }
        }
    }
}

// ======================= tensor-core flash attention =========================
// CTA = 128 queries of one (b,h); key tiles of 64; 8 warps (2M x 4N).
// QK':  S[128,64] = Q'[128,192] . K'[64,192]^T   (split bf16)
// PV':  O[128,64] += P'[128,192] . V'[64,192]^T  (V' is [d][k] transposed)
// smem: Q' 48K | K' 24K | V' 24K | P' 48K | S fp32 128x65 | m,l,f
#define AT_Q   0
#define AT_K   49152
#define AT_V   73728
#define AT_P   98304
#define AT_S   147456
#define AT_M   180736
#define AT_L   181248
#define AT_F   181760
#define AT_SMEM 182272
#define SSTR   65

__global__ __launch_bounds__(256) void attn_mma(
    __nv_bfloat16* __restrict__ Aout,
    const float* __restrict__ Qg, const float* __restrict__ Kg,
    const float* __restrict__ Vg)
{
    extern __shared__ char sm[];
    char*  Qb = sm + AT_Q;
    char*  Kb = sm + AT_K;
    char*  Vb = sm + AT_V;
    char*  Pb = sm + AT_P;
    float* Ss = (float*)(sm + AT_S);
    float* ms = (float*)(sm + AT_M);
    float* ls = (float*)(sm + AT_L);
    float* fs = (float*)(sm + AT_F);
    const uint32_t Qu = smem_u32(Qb), Ku = smem_u32(Kb);
    const uint32_t Vu = smem_u32(Vb), Pu = smem_u32(Pb);

    const int tid  = threadIdx.x;
    const int warp = tid >> 5;
    const int lane = tid & 31;
    const int wm   = warp & 1;
    const int wn   = warp >> 1;
    const int bh   = blockIdx.y;
    const int qt   = (int)gridDim.x - 1 - (int)blockIdx.x;  // heavy CTAs first
    const int q0   = qt * 128;

    if (tid < 128) { ms[tid] = -1e30f; ls[tid] = 0.0f; }

    // ---- build Q' (pre-scaled by 1/8), segs [qh | qh | ql] ----
    {
        const int r  = tid >> 1;
        const int d0 = (tid & 1) * 32;
        const float* qrow = Qg + ((size_t)bh * SEQ + q0 + r) * HDIM + d0;
#pragma unroll
        for (int dd = 0; dd < 32; dd += 2) {
            const float v0 = qrow[dd] * 0.125f, v1 = qrow[dd + 1] * 0.125f;
            const __nv_bfloat16 h0 = __float2bfloat16(v0);
            const __nv_bfloat16 h1 = __float2bfloat16(v1);
            const uint32_t hu = ((uint32_t)__bfloat16_as_ushort(h1) << 16)
                              | __bfloat16_as_ushort(h0);
            const uint32_t lu = pack_bf2(v0 - __bfloat162float(h0),
                                         v1 - __bfloat162float(h1));
            const int col = d0 + dd;
            *(uint32_t*)(Qb + sw384(r, col))       = hu;
            *(uint32_t*)(Qb + sw384(r, col + 64))  = hu;
            *(uint32_t*)(Qb + sw384(r, col + 128)) = lu;
        }
    }
    __syncthreads();

    // per-lane fragment terms (same mapping as validated GEMM)
    const int arow = (lane & 7) | (((lane >> 3) & 1) << 3);
    const int ach  = (lane >> 4) & 1;
    const int lq   = lane >> 3;
    const int bch  = lq & 1;
    const int bnrow = wn * 16 + ((lq >> 1) << 3) + (lane & 7);
    const int lsw  = lane & 7;   // row&7 for all frag rows
    uint32_t abase[4];
#pragma unroll
    for (int i = 0; i < 4; ++i)
        abase[i] = (uint32_t)((wm * 64 + i * 16 + arow) * 384);
    const uint32_t bbase = (uint32_t)(bnrow * 384);

    float acc_o[4][2][4];
#pragma unroll
    for (int i = 0; i < 4; ++i)
#pragma unroll
        for (int j = 0; j < 2; ++j)
#pragma unroll
            for (int r = 0; r < 4; ++r) acc_o[i][j][r] = 0.0f;

    const int ktmax = 2 * qt + 1;
    for (int kt = 0; kt <= ktmax; ++kt) {
        __syncthreads();   // prev PV done before overwriting K'/V'/P'

        // ---- convert K tile -> K' [kh | kl | kh] ----
        {
            const int k  = tid >> 2;
            const int d0 = (tid & 3) * 16;
            const float* krow = Kg + ((size_t)bh * SEQ + kt * 64 + k) * HDIM + d0;
#pragma unroll
            for (int dd = 0; dd < 16; dd += 2) {
                const float v0 = krow[dd], v1 = krow[dd + 1];
                const __nv_bfloat16 h0 = __float2bfloat16(v0);
                const __nv_bfloat16 h1 = __float2bfloat16(v1);
                const uint32_t hu = ((uint32_t)__bfloat16_as_ushort(h1) << 16)
                                  | __bfloat16_as_ushort(h0);
                const uint32_t lu = pack_bf2(v0 - __bfloat162float(h0),
                                             v1 - __bfloat162float(h1));
                const int col = d0 + dd;
                *(uint32_t*)(Kb + sw384(k, col))       = hu;
                *(uint32_t*)(Kb + sw384(k, col + 64))  = lu;
                *(uint32_t*)(Kb + sw384(k, col + 128)) = hu;
            }
        }
        // ---- convert V tile (transposed) -> V' rows=d: [vh | vl | vh] ----
        {
            const int k  = tid & 63;
            const int d0 = (tid >> 6) * 16;
            const float* vrow = Vg + ((size_t)bh * SEQ + kt * 64 + k) * HDIM + d0;
#pragma unroll
            for (int dd = 0; dd < 16; ++dd) {
                const float v = vrow[dd];
                const __nv_bfloat16 h = __float2bfloat16(v);
                const __nv_bfloat16 l = __float2bfloat16(v - __bfloat162float(h));
                const int d = d0 + dd;
                *(__nv_bfloat16*)(Vb + sw384(d, k))       = h;
                *(__nv_bfloat16*)(Vb + sw384(d, k + 64))  = l;
                *(__nv_bfloat16*)(Vb + sw384(d, k + 128)) = h;
            }
        }
        __syncthreads();

        // ---- S = Q' K'^T ----
        float acc_s[4][2][4];
#pragma unroll
        for (int i = 0; i < 4; ++i)
#pragma unroll
            for (int j = 0; j < 2; ++j)
#pragma unroll
                for (int r = 0; r < 4; ++r) acc_s[i][j][r] = 0.0f;

#pragma unroll
        for (int ks = 0; ks < 12; ++ks) {
            const int ua = ks * 2 + ach;
            const int ub = ks * 2 + bch;
            const uint32_t offA = (uint32_t)(((ua >> 3) << 7) + (((ua & 7) ^ lsw) << 4));
            const uint32_t offB = (uint32_t)(((ub >> 3) << 7) + (((ub & 7) ^ lsw) << 4));
            uint32_t af[4][4], bt[4];
#pragma unroll
            for (int i = 0; i < 4; ++i) ldsm4(af[i], Qu + abase[i] + offA);
            ldsm4(bt, Ku + bbase + offB);
            uint32_t bf0[2] = { bt[0], bt[1] }, bf1[2] = { bt[2], bt[3] };
#pragma unroll
            for (int i = 0; i < 4; ++i) {
                mma16816(acc_s[i][0], af[i], bf0);
                mma16816(acc_s[i][1], af[i], bf1);
            }
        }
        // store S to smem (fp32, stride 65 -> <=2-way conflicts)
        {
            const int g  = lane >> 2;
            const int cb = wn * 16 + (lane & 3) * 2;
#pragma unroll
            for (int i = 0; i < 4; ++i) {
                const int r0 = wm * 64 + i * 16 + g;
#pragma unroll
                for (int j = 0; j < 2; ++j) {
                    Ss[r0 * SSTR + cb + j * 8]           = acc_s[i][j][0];
                    Ss[r0 * SSTR + cb + j * 8 + 1]       = acc_s[i][j][1];
                    Ss[(r0 + 8) * SSTR + cb + j * 8]     = acc_s[i][j][2];
                    Ss[(r0 + 8) * SSTR + cb + j * 8 + 1] = acc_s[i][j][3];
                }
            }
        }
        __syncthreads();

        // ---- softmax: 2 threads per row, 32 cols each ----
        {
            const int r    = tid >> 1;
            const int half = tid & 1;
            const int gq   = q0 + r;
            const int kb   = kt * 64 + half * 32;
            float* srow = Ss + r * SSTR + half * 32;
            const bool nomask = (kb + 31 <= gq);

            float smax = -1e30f;
#pragma unroll
            for (int c = 0; c < 32; ++c) {
                float s = srow[c];
                if (!nomask && (kb + c > gq)) s = -1e30f;
                smax = fmaxf(smax, s);
            }
            smax = fmaxf(smax, __shfl_xor_sync(0xffffffffu, smax, 1));
            const float mo = ms[r];
            const float mn = fmaxf(mo, smax);

            float sum = 0.0f;
#pragma unroll
            for (int c = 0; c < 32; c += 2) {
                float s0 = srow[c], s1 = srow[c + 1];
                if (!nomask) {
                    if (kb + c     > gq) s0 = -1e30f;
                    if (kb + c + 1 > gq) s1 = -1e30f;
                }
                const float p0 = exp2p((s0 - mn) * LOG2E);
                const float p1 = exp2p((s1 - mn) * LOG2E);
                sum += p0 + p1;
                const __nv_bfloat16 h0 = __float2bfloat16(p0);
                const __nv_bfloat16 h1 = __float2bfloat16(p1);
                const uint32_t hu = ((uint32_t)__bfloat16_as_ushort(h1) << 16)
                                  | __bfloat16_as_ushort(h0);
                const uint32_t lu = pack_bf2(p0 - __bfloat162float(h0),
                                             p1 - __bfloat162float(h1));
                const int col = half * 32 + c;
                *(uint32_t*)(Pb + sw384(r, col))       = hu;
                *(uint32_t*)(Pb + sw384(r, col + 64))  = hu;
                *(uint32_t*)(Pb + sw384(r, col + 128)) = lu;
            }
            sum += __shfl_xor_sync(0xffffffffu, sum, 1);
            const float f = exp2p((mo - mn) * LOG2E);
            if (half == 0) {
                ms[r] = mn;
                ls[r] = ls[r] * f + sum;
                fs[r] = f;
            }
        }
        __syncthreads();

        // ---- O = O*f + P' V'^T ----
        {
            const int g = lane >> 2;
#pragma unroll
            for (int i = 0; i < 4; ++i) {
                const float f0 = fs[wm * 64 + i * 16 + g];
                const float f1 = fs[wm * 64 + i * 16 + g + 8];
#pragma unroll
                for (int j = 0; j < 2; ++j) {
                    acc_o[i][j][0] *= f0; acc_o[i][j][1] *= f0;
                    acc_o[i][j][2] *= f1; acc_o[i][j][3] *= f1;
                }
            }
        }
#pragma unroll
        for (int ks = 0; ks < 12; ++ks) {
            const int ua = ks * 2 + ach;
            const int ub = ks * 2 + bch;
            const uint32_t offA = (uint32_t)(((ua >> 3) << 7) + (((ua & 7) ^ lsw) << 4));
            const uint32_t offB = (uint32_t)(((ub >> 3) << 7) + (((ub & 7) ^ lsw) << 4));
            uint32_t af[4][4], bt[4];
#pragma unroll
            for (int i = 0; i < 4; ++i) ldsm4(af[i], Pu + abase[i] + offA);
            ldsm4(bt, Vu + bbase + offB);
            uint32_t bf0[2] = { bt[0], bt[1] }, bf1[2] = { bt[2], bt[3] };
#pragma unroll
            for (int i = 0; i < 4; ++i) {
                mma16816(acc_o[i][0], af[i], bf0);
                mma16816(acc_o[i][1], af[i], bf1);
            }
        }
    }

    // ---- epilogue: normalize, split, write [hi | hi | lo] to Aout ----
    {
        const int g = lane >> 2;
        const int b = bh >> 4;
        const int h = bh & 15;
#pragma unroll
        for (int i = 0; i < 4; ++i) {
            const int r0 = wm * 64 + i * 16 + g;
            const float inv0 = 1.0f / ls[r0];
            const float inv1 = 1.0f / ls[r0 + 8];
#pragma unroll
            for (int j = 0; j < 2; ++j) {
                const int d = wn * 16 + j * 8 + (lane & 3) * 2;
#pragma unroll
                for (int h2 = 0; h2 < 2; ++h2) {
                    const int   rr  = r0 + h2 * 8;
                    const float inv = h2 ? inv1 : inv0;
                    const float v0  = acc_o[i][j][h2 * 2]     * inv;
                    const float v1  = acc_o[i][j][h2 * 2 + 1] * inv;
                    const __nv_bfloat16 h0 = __float2bfloat16(v0);
                    const __nv_bfloat16 h1 = __float2bfloat16(v1);
                    const uint32_t hu = ((uint32_t)__bfloat16_as_ushort(h1) << 16)
                                      | __bfloat16_as_ushort(h0);
                    const uint32_t lu = pack_bf2(v0 - __bfloat162float(h0),
                                                 v1 - __bfloat162float(h1));
                    __nv_bfloat16* ap = Aout + ((size_t)b * SEQ + q0 + rr) * KP
                                      + h * HDIM + d;
                    *(uint32_t*)(ap)        = hu;
                    *(uint32_t*)(ap + 1024) = hu;
                    *(uint32_t*)(ap + 2048) = lu;
                }
            }
        }
    }
}

// ---------------------------------------------------------------------------
extern "C" void kernel_launch(void* const* d_in, const int* in_sizes, int n_in,
                              void* d_out, int out_size)
{
    const float* x  = (const float*)d_in[0];
    const float* Wq = (const float*)d_in[1];
    const float* Wk = (const float*)d_in[2];
    const float* Wv = (const float*)d_in[3];
    const float* Wo = (const float*)d_in[4];
    float* out = (float*)d_out;

    float *q, *k, *v;
    __nv_bfloat16 *ax, *bq, *bk, *bv, *bo, *aatt;
    cudaGetSymbolAddress((void**)&q,    g_Q);
    cudaGetSymbolAddress((void**)&k,    g_K);
    cudaGetSymbolAddress((void**)&v,    g_V);
    cudaGetSymbolAddress((void**)&ax,   g_Ax);
    cudaGetSymbolAddress((void**)&bq,   g_Bq);
    cudaGetSymbolAddress((void**)&bk,   g_Bk);
    cudaGetSymbolAddress((void**)&bv,   g_Bv);
    cudaGetSymbolAddress((void**)&bo,   g_Bo);
    cudaGetSymbolAddress((void**)&aatt, g_Aatt);

    split_kernel<<<MTOT, 256>>>(x, ax, 0);
    split_kernel<<<D_MODEL, 256>>>(Wq, bq, 1);
    split_kernel<<<D_MODEL, 256>>>(Wk, bk, 1);
    split_kernel<<<D_MODEL, 256>>>(Wv, bv, 1);
    split_kernel<<<D_MODEL, 256>>>(Wo, bo, 1);

    cudaFuncSetAttribute(gemm_mma,
                         cudaFuncAttributeMaxDynamicSharedMemorySize, SMEM_BYTES);
    const dim3 gg(D_MODEL / 128, MTOT / 128);   // (8, 32)

    gemm_mma<<<gg, 256, SMEM_BYTES>>>(ax, bq, q, 1);
    gemm_mma<<<gg, 256, SMEM_BYTES>>>(ax, bk, k, 1);
    gemm_mma<<<gg, 256, SMEM_BYTES>>>(ax, bv, v, 1);

    cudaFuncSetAttribute(attn_mma,
                         cudaFuncAttributeMaxDynamicSharedMemorySize, AT_SMEM);
    attn_mma<<<dim3(SEQ / 128, BATCH * NHEAD), 256, AT_SMEM>>>(aatt, q, k, v);

    gemm_mma<<<gg, 256, SMEM_BYTES>>>(aatt, bo, out, 0);
}

// round 9
// speedup vs baseline: 1.6273x; 1.6273x over previous
#include <cuda_runtime.h>
#include <cuda_bf16.h>
#include <math.h>
#include <stdint.h>

#define D_MODEL 1024
#define NHEAD   16
#define HDIM    64
#define SEQ     2048
#define BATCH   2
#define MTOT    (BATCH * SEQ)   // 4096
#define KP      3072            // split-bf16 K' = 3*1024
#define TK      64              // bf16 per K chunk (128 bytes)
#define NC      (KP / TK)       // 48 chunks
#define LOG2E   1.4426950408889634f

// ---------------- scratch (static device globals: allocation-free) ----------
__device__ float g_Q[BATCH * NHEAD * SEQ * HDIM];   // [b,h,s,d] fp32
__device__ float g_K[BATCH * NHEAD * SEQ * HDIM];
__device__ float g_V[BATCH * NHEAD * SEQ * HDIM];
__device__ __nv_bfloat16 g_Ax[MTOT * KP];           // split x    (A-mode)
__device__ __nv_bfloat16 g_Bq[D_MODEL * KP];        // split W    (B-mode)
__device__ __nv_bfloat16 g_Bk[D_MODEL * KP];
__device__ __nv_bfloat16 g_Bv[D_MODEL * KP];
__device__ __nv_bfloat16 g_Bo[D_MODEL * KP];
__device__ __nv_bfloat16 g_Aatt[MTOT * KP];         // split attn out (A-mode)
// attention operands, preconverted:
__device__ __nv_bfloat16 g_Qp[32 * SEQ * 128];          // [bh*2048+s][qh|ql]
__device__ __nv_bfloat16 g_Kp[32 * 32 * 64 * 128];      // [bh][kt] 16KB swizzled
__device__ __nv_bfloat16 g_Vp[32 * 32 * 64 * 128];      // [bh][kt] 16KB swizzled

// ============================ helpers ========================================
__device__ __forceinline__ uint32_t smem_u32(const void* p) {
    uint32_t a;
    asm("{ .reg .u64 t; cvta.to.shared.u64 t, %1; cvt.u32.u64 %0, t; }"
        : "=r"(a) : "l"(p));
    return a;
}
__device__ __forceinline__ void ldsm4(uint32_t* r, uint32_t addr) {
    asm volatile("ldmatrix.sync.aligned.m8n8.x4.shared.b16 {%0,%1,%2,%3}, [%4];"
                 : "=r"(r[0]), "=r"(r[1]), "=r"(r[2]), "=r"(r[3]) : "r"(addr));
}
__device__ __forceinline__ void mma16816(float* d, const uint32_t* a,
                                         const uint32_t* b) {
    asm volatile(
        "mma.sync.aligned.m16n8k16.row.col.f32.bf16.bf16.f32 "
        "{%0,%1,%2,%3}, {%4,%5,%6,%7}, {%8,%9}, {%0,%1,%2,%3};"
        : "+f"(d[0]), "+f"(d[1]), "+f"(d[2]), "+f"(d[3])
        : "r"(a[0]), "r"(a[1]), "r"(a[2]), "r"(a[3]), "r"(b[0]), "r"(b[1]));
}
__device__ __forceinline__ void cpa16(uint32_t dst, const void* src) {
    asm volatile("cp.async.cg.shared.global [%0], [%1], 16;"
                 :: "r"(dst), "l"(src));
}
#define CP_COMMIT() asm volatile("cp.async.commit_group;")
#define CP_WAIT0()  asm volatile("cp.async.wait_group 0;")

// 2^y on the FMA pipe; clamped so -huge -> ~1e-38 (≈0)
__device__ __forceinline__ float exp2p(float y) {
    y = fmaxf(y, -126.0f);
    const int   ni = __float2int_rn(y);
    const float f  = y - (float)ni;
    float p = 0.0096181f;
    p = fmaf(p, f, 0.0555041f);
    p = fmaf(p, f, 0.2402265f);
    p = fmaf(p, f, 0.6931472f);
    p = fmaf(p, f, 1.0f);
    return __int_as_float(__float_as_int(p) + (ni << 23));
}
__device__ __forceinline__ uint32_t pack_bf2(float a, float b) {
    return ((uint32_t)__bfloat16_as_ushort(__float2bfloat16(b)) << 16)
         | __bfloat16_as_ushort(__float2bfloat16(a));
}
__device__ __forceinline__ float bhi(float x) {
    return __bfloat162float(__float2bfloat16(x));
}
// byte offset in a 256B-row (128 bf16 col) XOR-swizzled tile
__device__ __forceinline__ uint32_t sw256(int row, int col) {
    return (uint32_t)(row * 256 + ((col >> 6) << 7)
                      + ((((col >> 3) & 7) ^ (row & 7)) << 4) + (col & 7) * 2);
}

// ============================ split kernel ===================================
// bmode 0 (A): [hi | hi | lo]     bmode 1 (B): [hi | lo | hi]
__global__ __launch_bounds__(256) void split_kernel(
    const float* __restrict__ src, __nv_bfloat16* __restrict__ dst, int bmode)
{
    const int idx = blockIdx.x * 256 + threadIdx.x;
    const int row = idx >> 8;
    const int c   = (idx & 255) * 4;
    float4 v = *(const float4*)(src + (size_t)row * 1024 + c);

    __nv_bfloat16 h0 = __float2bfloat16(v.x), h1 = __float2bfloat16(v.y);
    __nv_bfloat16 h2 = __float2bfloat16(v.z), h3 = __float2bfloat16(v.w);
    uint2 hu, lu;
    hu.x = ((uint32_t)__bfloat16_as_ushort(h1) << 16) | __bfloat16_as_ushort(h0);
    hu.y = ((uint32_t)__bfloat16_as_ushort(h3) << 16) | __bfloat16_as_ushort(h2);
    lu.x = pack_bf2(v.x - __bfloat162float(h0), v.y - __bfloat162float(h1));
    lu.y = pack_bf2(v.z - __bfloat162float(h2), v.w - __bfloat162float(h3));

    __nv_bfloat16* p = dst + (size_t)row * KP + c;
    if (bmode) {
        *(uint2*)(p) = hu; *(uint2*)(p + 1024) = lu; *(uint2*)(p + 2048) = hu;
    } else {
        *(uint2*)(p) = hu; *(uint2*)(p + 1024) = hu; *(uint2*)(p + 2048) = lu;
    }
}

// ============================ mma.sync GEMM (validated R5) ===================
#define SMEM_BYTES 65536

__device__ __forceinline__ void ldg_tiles(
    const __nv_bfloat16* __restrict__ A, const __nv_bfloat16* __restrict__ B,
    int bm, int bn, int c, int tid, float4* ar, float4* br)
{
#pragma unroll
    for (int j = 0; j < 4; ++j) {
        const int idx = j * 256 + tid, r = idx >> 3, s = idx & 7;
        ar[j] = *(const float4*)(A + (size_t)(bm + r) * KP + c * TK + s * 8);
        br[j] = *(const float4*)(B + (size_t)(bn + r) * KP + c * TK + s * 8);
    }
}
__device__ __forceinline__ void sts_tiles(
    char* smem, uint32_t pa, uint32_t pb, int tid,
    const float4* ar, const float4* br)
{
#pragma unroll
    for (int j = 0; j < 4; ++j) {
        const int idx = j * 256 + tid, r = idx >> 3, s = idx & 7;
        uint32_t off = (uint32_t)(r * 128 + s * 16);
        off ^= (off >> 3) & 0x70;
        *(float4*)(smem + pa + off) = ar[j];
        *(float4*)(smem + pb + off) = br[j];
    }
}

__global__ __launch_bounds__(256) void gemm_mma(
    const __nv_bfloat16* __restrict__ A, const __nv_bfloat16* __restrict__ B,
    float* __restrict__ C, int mode)
{
    extern __shared__ char smem[];
    const uint32_t sbase = smem_u32(smem);
    const int tid  = threadIdx.x;
    const int warp = tid >> 5;
    const int lane = tid & 31;
    const int bm   = blockIdx.y * 128;
    const int bn   = blockIdx.x * 128;
    const int wm   = warp & 1;
    const int wn   = warp >> 1;

    float4 ar[4], br[4];
    ldg_tiles(A, B, bm, bn, 0, tid, ar, br);
    sts_tiles(smem, 0, 32768, tid, ar, br);
    ldg_tiles(A, B, bm, bn, 1, tid, ar, br);
    __syncthreads();

    float acc[4][4][4];
#pragma unroll
    for (int i = 0; i < 4; ++i)
#pragma unroll
        for (int j = 0; j < 4; ++j)
#pragma unroll
            for (int r = 0; r < 4; ++r) acc[i][j][r] = 0.0f;

    const int arow = (lane & 7) | ((lane >> 3) & 1) << 3;
    const int ach  = (lane >> 4) & 1;
    uint32_t aterm[4]; int asw[4];
#pragma unroll
    for (int i = 0; i < 4; ++i) {
        const int row = wm * 64 + i * 16 + arow;
        aterm[i] = (uint32_t)(row * 128);
        asw[i]   = row & 7;
    }
    const int q   = lane >> 3;
    const int bch = q & 1;
    uint32_t bterm[2]; int bsw[2];
#pragma unroll
    for (int jj = 0; jj < 2; ++jj) {
        const int nrow = wn * 32 + jj * 16 + ((q >> 1) << 3) + (lane & 7);
        bterm[jj] = (uint32_t)(nrow * 128);
        bsw[jj]   = nrow & 7;
    }

    for (int c = 0; c < NC; ++c) {
        const int p = c & 1;
        const uint32_t Ab = sbase + (uint32_t)(p * 16384);
        const uint32_t Bb = sbase + 32768u + (uint32_t)(p * 16384);

        if (c + 1 < NC)
            sts_tiles(smem, (uint32_t)((p ^ 1) * 16384),
                      32768u + (uint32_t)((p ^ 1) * 16384), tid, ar, br);

#pragma unroll
        for (int ks = 0; ks < 4; ++ks) {
            const int k2 = ks * 2;
            uint32_t af[4][4], bf[4][2];
#pragma unroll
            for (int i = 0; i < 4; ++i)
                ldsm4(af[i], Ab + aterm[i] + ((uint32_t)((k2 + ach) ^ asw[i]) << 4));
#pragma unroll
            for (int jj = 0; jj < 2; ++jj) {
                uint32_t t[4];
                ldsm4(t, Bb + bterm[jj] + ((uint32_t)((k2 + bch) ^ bsw[jj]) << 4));
                bf[jj * 2 + 0][0] = t[0]; bf[jj * 2 + 0][1] = t[1];
                bf[jj * 2 + 1][0] = t[2]; bf[jj * 2 + 1][1] = t[3];
            }
#pragma unroll
            for (int i = 0; i < 4; ++i)
#pragma unroll
                for (int j = 0; j < 4; ++j)
                    mma16816(acc[i][j], af[i], bf[j]);
        }

        if (c + 2 < NC) ldg_tiles(A, B, bm, bn, c + 2, tid, ar, br);
        __syncthreads();
    }

    const int g   = lane >> 2;
    const int tig = lane & 3;
#pragma unroll
    for (int i = 0; i < 4; ++i) {
#pragma unroll
        for (int j = 0; j < 4; ++j) {
            const int col = bn + wn * 32 + j * 8 + tig * 2;
            const int m0  = bm + wm * 64 + i * 16 + g;
#pragma unroll
            for (int hrow = 0; hrow < 2; ++hrow) {
                const int m = m0 + hrow * 8;
                const float2 v = make_float2(acc[i][j][hrow * 2],
                                             acc[i][j][hrow * 2 + 1]);
                if (mode == 0) {
                    *(float2*)(C + (size_t)m * D_MODEL + col) = v;
                } else {
                    const int b = m >> 11, s2 = m & 2047;
                    const int h = col >> 6, dd = col & 63;
                    *(float2*)(C + ((((size_t)b * NHEAD + h) * SEQ + s2) * HDIM + dd)) = v;
                }
            }
        }
    }
}

// ======================= pre-convert kernels for attention ===================
// Q': plain rows [bh*2048+s][ qh(0-63) | ql(64-127) ], scaled by 1/8
// 65536 rows total, 4 threads/row -> launch 1024 blocks x 256 threads
__global__ __launch_bounds__(256) void conv_q(const float* __restrict__ Qg,
                                              __nv_bfloat16* __restrict__ Qp)
{
    const int gidx = blockIdx.x * 256 + threadIdx.x;
    const int row  = gidx >> 2;
    const int d0   = (gidx & 3) * 16;
    const float* src = Qg + (size_t)row * 64 + d0;
    __nv_bfloat16* dst = Qp + (size_t)row * 128 + d0;
#pragma unroll
    for (int dd = 0; dd < 16; dd += 2) {
        const float v0 = src[dd] * 0.125f, v1 = src[dd + 1] * 0.125f;
        const __nv_bfloat16 h0 = __float2bfloat16(v0);
        const __nv_bfloat16 h1 = __float2bfloat16(v1);
        *(uint32_t*)(dst + dd) = ((uint32_t)__bfloat16_as_ushort(h1) << 16)
                               | __bfloat16_as_ushort(h0);
        *(uint32_t*)(dst + 64 + dd) =
            pack_bf2(v0 - __bfloat162float(h0), v1 - __bfloat162float(h1));
    }
}
// K': per (bh,kt) 16KB swizzled tile [64 keys][ kh(d) | kl(d) ]
__global__ __launch_bounds__(128) void conv_k(const float* __restrict__ Kg,
                                              __nv_bfloat16* __restrict__ Kp)
{
    const int bh = blockIdx.y, kt = blockIdx.x, tid = threadIdx.x;
    char* dst = (char*)(Kp + ((size_t)bh * 32 + kt) * 8192);
    const int key = tid >> 1, d0 = (tid & 1) * 32;
    const float* src = Kg + (((size_t)bh * SEQ) + kt * 64 + key) * 64 + d0;
#pragma unroll
    for (int dd = 0; dd < 32; dd += 2) {
        const float v0 = src[dd], v1 = src[dd + 1];
        const __nv_bfloat16 h0 = __float2bfloat16(v0);
        const __nv_bfloat16 h1 = __float2bfloat16(v1);
        *(uint32_t*)(dst + sw256(key, d0 + dd)) =
            ((uint32_t)__bfloat16_as_ushort(h1) << 16) | __bfloat16_as_ushort(h0);
        *(uint32_t*)(dst + sw256(key, 64 + d0 + dd)) =
            pack_bf2(v0 - __bfloat162float(h0), v1 - __bfloat162float(h1));
    }
}
// V': per (bh,kt) 16KB swizzled tile, TRANSPOSED: [64 d][ vh(key) | vl(key) ]
__global__ __launch_bounds__(128) void conv_v(const float* __restrict__ Vg,
                                              __nv_bfloat16* __restrict__ Vp)
{
    const int bh = blockIdx.y, kt = blockIdx.x, tid = threadIdx.x;
    char* dst = (char*)(Vp + ((size_t)bh * 32 + kt) * 8192);
    const int key = tid >> 1, d0 = (tid & 1) * 32;
    const float* src = Vg + (((size_t)bh * SEQ) + kt * 64 + key) * 64 + d0;
#pragma unroll
    for (int dd = 0; dd < 32; ++dd) {
        const float v = src[dd];
        const __nv_bfloat16 h = __float2bfloat16(v);
        *(__nv_bfloat16*)(dst + sw256(d0 + dd, key)) = h;
        *(__nv_bfloat16*)(dst + sw256(d0 + dd, 64 + key)) =
            __float2bfloat16(v - __bfloat162float(h));
    }
}

// ======================= FA2 tensor-core attention ===========================
// CTA = 128 q-rows of one (b,h); 8 warps, warp owns 16 rows x ALL keys.
// Register softmax; P fragments packed from S accumulators.
// smem 64KB: buf0 [K 16K | V 16K], buf1 [K | V] (buf1 aliases Q staging).
__device__ __forceinline__ void bpass(
    float acc[8][4], const uint32_t a[4][4], uint32_t bufu, int segcol,
    int rbase, int bch)
{
#pragma unroll
    for (int t = 0; t < 4; ++t) {
        uint32_t bf[8][2];
#pragma unroll
        for (int jj = 0; jj < 4; ++jj) {
            uint32_t bt[4];
            ldsm4(bt, bufu + sw256(jj * 16 + rbase, segcol + t * 16 + bch * 8));
            bf[jj * 2 + 0][0] = bt[0]; bf[jj * 2 + 0][1] = bt[1];
            bf[jj * 2 + 1][0] = bt[2]; bf[jj * 2 + 1][1] = bt[3];
        }
#pragma unroll
        for (int j = 0; j < 8; ++j) mma16816(acc[j], a[t], bf[j]);
    }
}

__global__ __launch_bounds__(256) void attn_fa2(
    __nv_bfloat16* __restrict__ Aout,
    const __nv_bfloat16* __restrict__ Qp,
    const __nv_bfloat16* __restrict__ Kp,
    const __nv_bfloat16* __restrict__ Vp)
{
    extern __shared__ char sm[];
    const uint32_t sbase = smem_u32(sm);
    const int tid  = threadIdx.x;
    const int warp = tid >> 5;
    const int lane = tid & 31;
    const int bh   = blockIdx.y;
    const int qt   = (int)gridDim.x - 1 - (int)blockIdx.x;   // heavy first
    const int q0   = qt * 128;
    const int ktmax = 2 * qt + 1;

    // prefetch tile 0 -> buf0 (K 16K + V 16K, contiguous pre-swizzled)
    {
        const char* ksrc = (const char*)(Kp + ((size_t)bh * 32) * 8192);
        const char* vsrc = (const char*)(Vp + ((size_t)bh * 32) * 8192);
#pragma unroll
        for (int i = 0; i < 4; ++i) {
            const uint32_t off = (uint32_t)(i * 4096 + tid * 16);
            cpa16(sbase + off, ksrc + off);
            cpa16(sbase + 16384u + off, vsrc + off);
        }
        CP_COMMIT();
    }

    // stage Q' into buf1 area (swizzled), then ldsm into registers
    const uint32_t stage = sbase + 32768u;
    {
        const __nv_bfloat16* qsrc = Qp + ((size_t)bh * SEQ + q0) * 128;
#pragma unroll
        for (int i = 0; i < 8; ++i) {
            const int c    = i * 256 + tid;        // 16B chunk id
            const int row  = c >> 4;
            const int col8 = (c & 15) * 8;
            const uint4 v = *(const uint4*)(qsrc + (size_t)row * 128 + col8);
            *(uint4*)(sm + 32768 + sw256(row, col8)) = v;
        }
    }
    __syncthreads();

    const int arow  = (lane & 7) | (((lane >> 3) & 1) << 3);
    const int ach   = (lane >> 4) & 1;
    const int lq    = lane >> 3;
    const int bch   = lq & 1;
    const int rbase = ((lq >> 1) << 3) + (lane & 7);
    const int g     = lane >> 2;
    const int tig   = lane & 3;

    uint32_t aQh[4][4], aQl[4][4];
#pragma unroll
    for (int t = 0; t < 4; ++t) {
        ldsm4(aQh[t], stage + sw256(warp * 16 + arow, t * 16 + ach * 8));
        ldsm4(aQl[t], stage + sw256(warp * 16 + arow, 64 + t * 16 + ach * 8));
    }

    float acc_o[8][4];
#pragma unroll
    for (int j = 0; j < 8; ++j)
#pragma unroll
        for (int r = 0; r < 4; ++r) acc_o[j][r] = 0.0f;
    float m0 = -1e30f, m1 = -1e30f, l0 = 0.0f, l1 = 0.0f;

    const int row0 = q0 + warp * 16 + g;
    const int row1 = row0 + 8;

    for (int kt = 0; kt <= ktmax; ++kt) {
        CP_WAIT0();
        __syncthreads();   // tile kt visible to all; buf[(kt+1)&1] free

        if (kt < ktmax) {
            const char* ksrc = (const char*)(Kp + ((size_t)bh * 32 + kt + 1) * 8192);
            const char* vsrc = (const char*)(Vp + ((size_t)bh * 32 + kt + 1) * 8192);
            const uint32_t dst = sbase + (uint32_t)(((kt + 1) & 1) * 32768);
#pragma unroll
            for (int i = 0; i < 4; ++i) {
                const uint32_t off = (uint32_t)(i * 4096 + tid * 16);
                cpa16(dst + off, ksrc + off);
                cpa16(dst + 16384u + off, vsrc + off);
            }
            CP_COMMIT();
        }

        const uint32_t Kb = sbase + (uint32_t)((kt & 1) * 32768);
        const uint32_t Vb = Kb + 16384u;

        // ---- S = qh.kh + qh.kl + ql.kh ----
        float acc_s[8][4];
#pragma unroll
        for (int j = 0; j < 8; ++j)
#pragma unroll
            for (int r = 0; r < 4; ++r) acc_s[j][r] = 0.0f;
        bpass(acc_s, aQh, Kb, 0,  rbase, bch);
        bpass(acc_s, aQh, Kb, 64, rbase, bch);
        bpass(acc_s, aQl, Kb, 0,  rbase, bch);

        // ---- causal mask (only near the diagonal of this warp) ----
        if (kt * 64 + 63 > row0) {
#pragma unroll
            for (int j = 0; j < 8; ++j) {
                const int col = kt * 64 + j * 8 + tig * 2;
                if (col     > row0) acc_s[j][0] = -1e30f;
                if (col + 1 > row0) acc_s[j][1] = -1e30f;
                if (col     > row1) acc_s[j][2] = -1e30f;
                if (col + 1 > row1) acc_s[j][3] = -1e30f;
            }
        }

        // ---- register softmax ----
        float mx0 = -1e30f, mx1 = -1e30f;
#pragma unroll
        for (int j = 0; j < 8; ++j) {
            mx0 = fmaxf(mx0, fmaxf(acc_s[j][0], acc_s[j][1]));
            mx1 = fmaxf(mx1, fmaxf(acc_s[j][2], acc_s[j][3]));
        }
        mx0 = fmaxf(mx0, __shfl_xor_sync(0xffffffffu, mx0, 1));
        mx0 = fmaxf(mx0, __shfl_xor_sync(0xffffffffu, mx0, 2));
        mx1 = fmaxf(mx1, __shfl_xor_sync(0xffffffffu, mx1, 1));
        mx1 = fmaxf(mx1, __shfl_xor_sync(0xffffffffu, mx1, 2));
        const float mn0 = fmaxf(m0, mx0), mn1 = fmaxf(m1, mx1);
        const float f0  = exp2p((m0 - mn0) * LOG2E);
        const float f1  = exp2p((m1 - mn1) * LOG2E);
        m0 = mn0; m1 = mn1;

        float s0 = 0.0f, s1 = 0.0f;
#pragma unroll
        for (int j = 0; j < 8; ++j) {
            acc_s[j][0] = exp2p((acc_s[j][0] - mn0) * LOG2E);
            acc_s[j][1] = exp2p((acc_s[j][1] - mn0) * LOG2E);
            acc_s[j][2] = exp2p((acc_s[j][2] - mn1) * LOG2E);
            acc_s[j][3] = exp2p((acc_s[j][3] - mn1) * LOG2E);
            s0 += acc_s[j][0] + acc_s[j][1];
            s1 += acc_s[j][2] + acc_s[j][3];
        }
        s0 += __shfl_xor_sync(0xffffffffu, s0, 1);
        s0 += __shfl_xor_sync(0xffffffffu, s0, 2);
        s1 += __shfl_xor_sync(0xffffffffu, s1, 1);
        s1 += __shfl_xor_sync(0xffffffffu, s1, 2);
        l0 = l0 * f0 + s0;
        l1 = l1 * f1 + s1;
#pragma unroll
        for (int j = 0; j < 8; ++j) {
            acc_o[j][0] *= f0; acc_o[j][1] *= f0;
            acc_o[j][2] *= f1; acc_o[j][3] *= f1;
        }

        // ---- P fragments straight from registers ----
        uint32_t aPh[4][4];
#pragma unroll
        for (int t = 0; t < 4; ++t) {
            aPh[t][0] = pack_bf2(acc_s[2 * t][0],     acc_s[2 * t][1]);
            aPh[t][1] = pack_bf2(acc_s[2 * t][2],     acc_s[2 * t][3]);
            aPh[t][2] = pack_bf2(acc_s[2 * t + 1][0], acc_s[2 * t + 1][1]);
            aPh[t][3] = pack_bf2(acc_s[2 * t + 1][2], acc_s[2 * t + 1][3]);
        }
        // O += ph.vh + ph.vl
        bpass(acc_o, aPh, Vb, 0,  rbase, bch);
        bpass(acc_o, aPh, Vb, 64, rbase, bch);
        // O += pl.vh
        uint32_t aPl[4][4];
#pragma unroll
        for (int t = 0; t < 4; ++t) {
            aPl[t][0] = pack_bf2(acc_s[2 * t][0] - bhi(acc_s[2 * t][0]),
                                 acc_s[2 * t][1] - bhi(acc_s[2 * t][1]));
            aPl[t][1] = pack_bf2(acc_s[2 * t][2] - bhi(acc_s[2 * t][2]),
                                 acc_s[2 * t][3] - bhi(acc_s[2 * t][3]));
            aPl[t][2] = pack_bf2(acc_s[2 * t + 1][0] - bhi(acc_s[2 * t + 1][0]),
                                 acc_s[2 * t + 1][1] - bhi(acc_s[2 * t + 1][1]));
            aPl[t][3] = pack_bf2(acc_s[2 * t + 1][2] - bhi(acc_s[2 * t + 1][2]),
                                 acc_s[2 * t + 1][3] - bhi(acc_s[2 * t + 1][3]));
        }
        bpass(acc_o, aPl, Vb, 0, rbase, bch);
    }

    // ---- epilogue: normalize, split, write [hi | hi | lo] to Aout ----
    const int b   = bh >> 4;
    const int h   = bh & 15;
    const float inv0 = 1.0f / l0, inv1 = 1.0f / l1;
#pragma unroll
    for (int j = 0; j < 8; ++j) {
        const int d = j * 8 + tig * 2;
#pragma unroll
        for (int h2 = 0; h2 < 2; ++h2) {
            const int   rr  = (h2 ? row1 : row0);
            const float inv = (h2 ? inv1 : inv0);
            const float v0  = acc_o[j][h2 * 2]     * inv;
            const float v1  = acc_o[j][h2 * 2 + 1] * inv;
            const __nv_bfloat16 h0 = __float2bfloat16(v0);
            const __nv_bfloat16 h1 = __float2bfloat16(v1);
            const uint32_t hu = ((uint32_t)__bfloat16_as_ushort(h1) << 16)
                              | __bfloat16_as_ushort(h0);
            const uint32_t lu = pack_bf2(v0 - __bfloat162float(h0),
                                         v1 - __bfloat162float(h1));
            __nv_bfloat16* ap = Aout + ((size_t)b * SEQ + rr) * KP + h * HDIM + d;
            *(uint32_t*)(ap)        = hu;
            *(uint32_t*)(ap + 1024) = hu;
            *(uint32_t*)(ap + 2048) = lu;
        }
    }
}

// ---------------------------------------------------------------------------
extern "C" void kernel_launch(void* const* d_in, const int* in_sizes, int n_in,
                              void* d_out, int out_size)
{
    const float* x  = (const float*)d_in[0];
    const float* Wq = (const float*)d_in[1];
    const float* Wk = (const float*)d_in[2];
    const float* Wv = (const float*)d_in[3];
    const float* Wo = (const float*)d_in[4];
    float* out = (float*)d_out;

    float *q, *k, *v;
    __nv_bfloat16 *ax, *bq, *bk, *bv, *bo, *aatt, *qp, *kp, *vp;
    cudaGetSymbolAddress((void**)&q,    g_Q);
    cudaGetSymbolAddress((void**)&k,    g_K);
    cudaGetSymbolAddress((void**)&v,    g_V);
    cudaGetSymbolAddress((void**)&ax,   g_Ax);
    cudaGetSymbolAddress((void**)&bq,   g_Bq);
    cudaGetSymbolAddress((void**)&bk,   g_Bk);
    cudaGetSymbolAddress((void**)&bv,   g_Bv);
    cudaGetSymbolAddress((void**)&bo,   g_Bo);
    cudaGetSymbolAddress((void**)&aatt, g_Aatt);
    cudaGetSymbolAddress((void**)&qp,   g_Qp);
    cudaGetSymbolAddress((void**)&kp,   g_Kp);
    cudaGetSymbolAddress((void**)&vp,   g_Vp);

    split_kernel<<<MTOT, 256>>>(x, ax, 0);
    split_kernel<<<D_MODEL, 256>>>(Wq, bq, 1);
    split_kernel<<<D_MODEL, 256>>>(Wk, bk, 1);
    split_kernel<<<D_MODEL, 256>>>(Wv, bv, 1);
    split_kernel<<<D_MODEL, 256>>>(Wo, bo, 1);

    cudaFuncSetAttribute(gemm_mma,
                         cudaFuncAttributeMaxDynamicSharedMemorySize, SMEM_BYTES);
    const dim3 gg(D_MODEL / 128, MTOT / 128);   // (8, 32)

    gemm_mma<<<gg, 256, SMEM_BYTES>>>(ax, bq, q, 1);
    gemm_mma<<<gg, 256, SMEM_BYTES>>>(ax, bk, k, 1);
    gemm_mma<<<gg, 256, SMEM_BYTES>>>(ax, bv, v, 1);

    // FIX (R7 bug): 32*2048 = 65536 rows x 4 threads = 262144 threads
    conv_q<<<1024, 256>>>(q, qp);
    conv_k<<<dim3(32, 32), 128>>>(k, kp);
    conv_v<<<dim3(32, 32), 128>>>(v, vp);

    cudaFuncSetAttribute(attn_fa2,
                         cudaFuncAttributeMaxDynamicSharedMemorySize, 65536);
    attn_fa2<<<dim3(SEQ / 128, BATCH * NHEAD), 256, 65536>>>(aatt, qp, kp, vp);

    gemm_mma<<<gg, 256, SMEM_BYTES>>>(aatt, bo, out, 0);
}